// round 9
// baseline (speedup 1.0000x reference)
#include <cuda_runtime.h>

// ---------------------------------------------------------------------------
// EnhancedReconstructionLoss: 0.8*MSE + 0.2*(1 - mean(SSIM_map)), fused.
//
// s/d reformulation (s=x+y, d=x-y) -> 4 window sums (Ws,Wd,Wss,Wdd):
//   N1 = (Ws^2-Wd^2) + 162*C1          N2 = 9(Wss-Wdd) - (Ws^2-Wd^2) + 162*C2
//   D1 = (Ws^2+Wd^2) + 162*C1          D2 = 9(Wss+Wdd) - (Ws^2+Wd^2) + 162*C2
//   ssim = N1*N2 / (D1*D2 + 4*6561*eps)
//
// R9: 4-slot convert-on-load window (distance-1 load decoupling WITHOUT a raw
// register buffer) + L2 prefetch hints + sub.f32x2 + packed halo sums, forced
// to 5 CTAs/SM via launch_bounds(128,5).
// ---------------------------------------------------------------------------

typedef unsigned long long u64;

#define IMW 512
#define IMH 512
#define NPLANES 96
#define RPW 16                    // rows per warp-task
#define STRIPS 32                 // 512 / 16
#define WPB 4                     // warps per block
#define NBLOCKS (NPLANES * STRIPS * 2 / WPB)   // 1536
#define NTOTD 25165824.0          // 32*3*512*512

__device__ float g_mse_acc  = 0.f;
__device__ float g_ssim_acc = 0.f;
__device__ unsigned int g_cnt = 0u;

__device__ __forceinline__ u64 f2_pack(float lo, float hi) {
    u64 r; asm("mov.b64 %0, {%1, %2};" : "=l"(r) : "f"(lo), "f"(hi)); return r;
}
__device__ __forceinline__ void f2_unpack(u64 p, float& lo, float& hi) {
    asm("mov.b64 {%0, %1}, %2;" : "=f"(lo), "=f"(hi) : "l"(p));
}
__device__ __forceinline__ u64 f2_set(float v) { return f2_pack(v, v); }
__device__ __forceinline__ u64 add2(u64 a, u64 b) {
    u64 d; asm("add.rn.f32x2 %0, %1, %2;" : "=l"(d) : "l"(a), "l"(b)); return d;
}
__device__ __forceinline__ u64 sub2(u64 a, u64 b) {
    u64 d; asm("sub.rn.f32x2 %0, %1, %2;" : "=l"(d) : "l"(a), "l"(b)); return d;
}
__device__ __forceinline__ u64 mul2(u64 a, u64 b) {
    u64 d; asm("mul.rn.f32x2 %0, %1, %2;" : "=l"(d) : "l"(a), "l"(b)); return d;
}
__device__ __forceinline__ u64 fma2(u64 a, u64 b, u64 c) {
    u64 d; asm("fma.rn.f32x2 %0, %1, %2, %3;" : "=l"(d) : "l"(a), "l"(b), "l"(c)); return d;
}

// Horizontal 3-sum over 8 columns (4 packed u64), warp-shuffle neighbors plus
// scalar halo vH at the warp's interior boundary.
__device__ __forceinline__ void hsum8(const u64 v0, const u64 v1, const u64 v2, const u64 v3,
                                      float vH, int lane, int half,
                                      u64& H0, u64& H1, u64& H2, u64& H3) {
    float f0, f1, f2, f3, f4, f5, f6, f7;
    f2_unpack(v0, f0, f1);
    f2_unpack(v1, f2, f3);
    f2_unpack(v2, f4, f5);
    f2_unpack(v3, f6, f7);
    float up = __shfl_up_sync(0xffffffffu, f7, 1);
    float dn = __shfl_down_sync(0xffffffffu, f0, 1);
    float nl = (lane == 0)  ? (half ? vH : 0.f) : up;
    float nr = (lane == 31) ? (half ? 0.f : vH) : dn;
    u64 L0 = f2_pack(nl, f0);
    u64 L1 = f2_pack(f1, f2);
    u64 L2 = f2_pack(f3, f4);
    u64 L3 = f2_pack(f5, f6);
    u64 R3 = f2_pack(f7, nr);
    H0 = add2(add2(L0, v0), L1);
    H1 = add2(add2(L1, v1), L2);
    H2 = add2(add2(L2, v2), L3);
    H3 = add2(add2(L3, v3), R3);
}

__global__ void __launch_bounds__(128, 5)
loss_fused(const float* __restrict__ X, const float* __restrict__ Y,
           float* __restrict__ out) {
    const int w    = threadIdx.x >> 5;
    const int lane = threadIdx.x & 31;
    const int task  = blockIdx.x * WPB + w;
    const int half  = task & 1;
    const int strip = (task >> 1) & (STRIPS - 1);
    const int plane = task >> 6;
    const int R0 = strip * RPW;
    const int c0 = half * 256 + (lane << 3);

    const float* px = X + (size_t)plane * (IMW * IMH) + c0;
    const float* py = Y + (size_t)plane * (IMW * IMH) + c0;

    const bool hval = (lane == 0) ? (half == 1)
                    : ((lane == 31) ? (half == 0) : false);
    const int hoff = (lane == 0) ? -1 : 8;

    const u64 k9   = f2_set(9.0f);
    const u64 kC1  = f2_set(0.0162f);      // 162 * C1
    const u64 kC2  = f2_set(0.1458f);      // 162 * C2
    const u64 kEPS = f2_set(2.6244e-4f);   // 4 * 6561 * eps

    // 4-slot rolling window of s,d rows (8 cols = 4 u64 each); halo per slot
    // stored packed as (hs, hd).
    u64 ws[4][4], wdv[4][4];
    u64 whsd[4];

    // L2 prefetch hint for window row j (zero registers).
    auto PF = [&](int j) {
        int gr = R0 - 1 + j;
        gr = (gr < IMH) ? gr : (IMH - 1);   // clamp; only a hint
        const float* ax = px + (size_t)gr * IMW;
        const float* ay = py + (size_t)gr * IMW;
        asm volatile("prefetch.global.L2 [%0];" :: "l"(ax));
        asm volatile("prefetch.global.L2 [%0];" :: "l"(ay));
    };

    // Load row gr = R0-1+j and convert straight into window slot j&3.
    // Placed at the END of each iteration: results are consumed only next
    // iteration, so LDGs get hoisted and stay in flight a full iteration.
    auto LOADCVT = [&](int j) {
        const int slot = j & 3;
        const int gr = R0 - 1 + j;
        const bool v = ((unsigned)gr < (unsigned)IMH);
        float4 xa = make_float4(0.f, 0.f, 0.f, 0.f), xb = xa, ya = xa, yb = xa;
        float hx = 0.f, hy = 0.f;
        if (v) {
            const float4* p4 = reinterpret_cast<const float4*>(px + (size_t)gr * IMW);
            const float4* q4 = reinterpret_cast<const float4*>(py + (size_t)gr * IMW);
            xa = p4[0]; xb = p4[1];
            ya = q4[0]; yb = q4[1];
            if (hval) {
                hx = px[(size_t)gr * IMW + hoff];
                hy = py[(size_t)gr * IMW + hoff];
            }
        }
        u64 xp0 = f2_pack(xa.x, xa.y), xp1 = f2_pack(xa.z, xa.w);
        u64 xp2 = f2_pack(xb.x, xb.y), xp3 = f2_pack(xb.z, xb.w);
        u64 yp0 = f2_pack(ya.x, ya.y), yp1 = f2_pack(ya.z, ya.w);
        u64 yp2 = f2_pack(yb.x, yb.y), yp3 = f2_pack(yb.z, yb.w);
        ws[slot][0] = add2(xp0, yp0);   wdv[slot][0] = sub2(xp0, yp0);
        ws[slot][1] = add2(xp1, yp1);   wdv[slot][1] = sub2(xp1, yp1);
        ws[slot][2] = add2(xp2, yp2);   wdv[slot][2] = sub2(xp2, yp2);
        ws[slot][3] = add2(xp3, yp3);   wdv[slot][3] = sub2(xp3, yp3);
        whsd[slot] = f2_pack(hx + hy, hx - hy);
    };

    PF(3); PF(4);                  // warm L2 ahead of the pipeline
    LOADCVT(0); LOADCVT(1); LOADCVT(2);

    u64 mAcc0 = f2_set(0.f), mAcc1 = f2_set(0.f);
    float sA0 = 0.f, sA1 = 0.f;

#pragma unroll
    for (int r = 0; r < RPW; ++r) {
        const int j0 = r & 3, j1 = (r + 1) & 3, j2 = (r + 2) & 3;

        // halo vertical sums, fully packed: (vHs,vHd) and (vHss,vHdd)
        u64 h0 = whsd[j0], h1 = whsd[j1], h2 = whsd[j2];
        u64 vH1 = add2(add2(h0, h1), h2);
        u64 vH2 = fma2(h0, h0, fma2(h1, h1, mul2(h2, h2)));
        float vHs, vHd, vHss, vHdd;
        f2_unpack(vH1, vHs, vHd);
        f2_unpack(vH2, vHss, vHdd);

        // ---- Ws, Wd first; derive T1/T2; release transients early ----
        u64 T1[4], T2[4];
        {
            u64 Vq[4], Hq[4];
#pragma unroll
            for (int k = 0; k < 4; ++k)
                Vq[k] = add2(add2(ws[j0][k], ws[j1][k]), ws[j2][k]);
            hsum8(Vq[0], Vq[1], Vq[2], Vq[3], vHs, lane, half,
                  Hq[0], Hq[1], Hq[2], Hq[3]);
            u64 Es[4];
#pragma unroll
            for (int k = 0; k < 4; ++k) Es[k] = mul2(Hq[k], Hq[k]);   // Ws^2
#pragma unroll
            for (int k = 0; k < 4; ++k)
                Vq[k] = add2(add2(wdv[j0][k], wdv[j1][k]), wdv[j2][k]);
            hsum8(Vq[0], Vq[1], Vq[2], Vq[3], vHd, lane, half,
                  Hq[0], Hq[1], Hq[2], Hq[3]);
#pragma unroll
            for (int k = 0; k < 4; ++k) {
                u64 F = mul2(Hq[k], Hq[k]);            // Wd^2
                T1[k] = sub2(Es[k], F);                // Ws^2 - Wd^2
                T2[k] = add2(Es[k], F);                // Ws^2 + Wd^2
            }
        }

        // ---- Wss, Wdd; finish the rational ----
        {
            u64 Vss[4], Vdd[4], Hss[4], Hdd[4];
#pragma unroll
            for (int k = 0; k < 4; ++k) {
                u64 s0 = ws[j0][k], s1 = ws[j1][k], s2 = ws[j2][k];
                Vss[k] = fma2(s0, s0, fma2(s1, s1, mul2(s2, s2)));
            }
            hsum8(Vss[0], Vss[1], Vss[2], Vss[3], vHss, lane, half,
                  Hss[0], Hss[1], Hss[2], Hss[3]);
#pragma unroll
            for (int k = 0; k < 4; ++k) {
                u64 d0 = wdv[j0][k], d1 = wdv[j1][k], d2 = wdv[j2][k];
                Vdd[k] = fma2(d0, d0, fma2(d1, d1, mul2(d2, d2)));
            }
            hsum8(Vdd[0], Vdd[1], Vdd[2], Vdd[3], vHdd, lane, half,
                  Hdd[0], Hdd[1], Hdd[2], Hdd[3]);
#pragma unroll
            for (int k = 0; k < 4; ++k) {
                u64 N1 = add2(T1[k], kC1);
                u64 D1 = add2(T2[k], kC1);
                u64 U1 = sub2(Hss[k], Hdd[k]);         // Wss - Wdd
                u64 U2 = add2(Hss[k], Hdd[k]);
                u64 N2 = sub2(fma2(U1, k9, kC2), T1[k]);
                u64 D2 = sub2(fma2(U2, k9, kC2), T2[k]);
                u64 num = mul2(N1, N2);
                u64 den = fma2(D1, D2, kEPS);
                float n0, n1, d0, d1;
                f2_unpack(num, n0, n1);
                f2_unpack(den, d0, d1);
                sA0 += __fdividef(n0, d0);
                sA1 += __fdividef(n1, d1);
            }
        }

        // ---- MSE on the center row (input row R0+r = slot j1) ----
        mAcc0 = fma2(wdv[j1][0], wdv[j1][0], mAcc0);
        mAcc0 = fma2(wdv[j1][1], wdv[j1][1], mAcc0);
        mAcc1 = fma2(wdv[j1][2], wdv[j1][2], mAcc1);
        mAcc1 = fma2(wdv[j1][3], wdv[j1][3], mAcc1);

        // ---- load next window row (consumed next iteration) ----
        if (r < RPW - 1) LOADCVT(r + 3);
        if (r + 5 <= RPW + 1) PF(r + 5);
    }

    // ---- reductions ----
    float m0, m1, m2, m3;
    f2_unpack(mAcc0, m0, m1);
    f2_unpack(mAcc1, m2, m3);
    float mAcc = (m0 + m1) + (m2 + m3);
    float sAcc = sA0 + sA1;
#pragma unroll
    for (int o = 16; o; o >>= 1) {
        mAcc += __shfl_xor_sync(0xffffffffu, mAcc, o);
        sAcc += __shfl_xor_sync(0xffffffffu, sAcc, o);
    }
    __shared__ float shm[WPB], shs[WPB];
    if (lane == 0) { shm[w] = mAcc; shs[w] = sAcc; }
    __syncthreads();
    if (threadIdx.x == 0) {
        float M = (shm[0] + shm[1]) + (shm[2] + shm[3]);
        float S = (shs[0] + shs[1]) + (shs[2] + shs[3]);
        atomicAdd(&g_mse_acc, M);
        atomicAdd(&g_ssim_acc, S);
        __threadfence();
        unsigned c = atomicInc(&g_cnt, NBLOCKS - 1);   // wraps to 0 on last
        if (c == NBLOCKS - 1) {
            __threadfence();
            float Mt = atomicExch(&g_mse_acc, 0.f);
            float St = atomicExch(&g_ssim_acc, 0.f);
            double mse  = (double)Mt / NTOTD;
            double ssim = (double)St / NTOTD;
            out[0] = (float)(0.8 * mse + 0.2 * (1.0 - ssim));
        }
    }
}

extern "C" void kernel_launch(void* const* d_in, const int* in_sizes, int n_in,
                              void* d_out, int out_size) {
    const float* X = (const float*)d_in[0];
    const float* Y = (const float*)d_in[1];
    loss_fused<<<NBLOCKS, 128>>>(X, Y, (float*)d_out);
}

// round 10
// speedup vs baseline: 1.0551x; 1.0551x over previous
#include <cuda_runtime.h>

// ---------------------------------------------------------------------------
// EnhancedReconstructionLoss: 0.8*MSE + 0.2*(1 - mean(SSIM_map)), fused.
//
// s/d reformulation (s=x+y, d=x-y) -> 4 window sums (Ws,Wd,Wss,Wdd):
//   N1 = (Ws^2-Wd^2) + 162*C1          N2 = 9(Wss-Wdd) - (Ws^2-Wd^2) + 162*C2
//   D1 = (Ws^2+Wd^2) + 162*C1          D2 = 9(Wss+Wdd) - (Ws^2+Wd^2) + 162*C2
//   ssim = N1*N2 / (D1*D2 + 4*6561*eps)
//
// R10: TWO output rows per iteration from a 4-slot window. Shared middle-pair
// vertical partials, two independent dependency chains per iteration (2x ILP),
// one load block per iteration, L2 prefetch hints. launch_bounds(128,4).
// ---------------------------------------------------------------------------

typedef unsigned long long u64;

#define IMW 512
#define IMH 512
#define NPLANES 96
#define RPW 16                    // rows per warp-task
#define STRIPS 32                 // 512 / 16
#define WPB 4                     // warps per block
#define NBLOCKS (NPLANES * STRIPS * 2 / WPB)   // 1536
#define NTOTD 25165824.0          // 32*3*512*512

__device__ float g_mse_acc  = 0.f;
__device__ float g_ssim_acc = 0.f;
__device__ unsigned int g_cnt = 0u;

__device__ __forceinline__ u64 f2_pack(float lo, float hi) {
    u64 r; asm("mov.b64 %0, {%1, %2};" : "=l"(r) : "f"(lo), "f"(hi)); return r;
}
__device__ __forceinline__ void f2_unpack(u64 p, float& lo, float& hi) {
    asm("mov.b64 {%0, %1}, %2;" : "=f"(lo), "=f"(hi) : "l"(p));
}
__device__ __forceinline__ u64 f2_set(float v) { return f2_pack(v, v); }
__device__ __forceinline__ u64 add2(u64 a, u64 b) {
    u64 d; asm("add.rn.f32x2 %0, %1, %2;" : "=l"(d) : "l"(a), "l"(b)); return d;
}
__device__ __forceinline__ u64 sub2(u64 a, u64 b) {
    u64 d; asm("sub.rn.f32x2 %0, %1, %2;" : "=l"(d) : "l"(a), "l"(b)); return d;
}
__device__ __forceinline__ u64 mul2(u64 a, u64 b) {
    u64 d; asm("mul.rn.f32x2 %0, %1, %2;" : "=l"(d) : "l"(a), "l"(b)); return d;
}
__device__ __forceinline__ u64 fma2(u64 a, u64 b, u64 c) {
    u64 d; asm("fma.rn.f32x2 %0, %1, %2, %3;" : "=l"(d) : "l"(a), "l"(b), "l"(c)); return d;
}

// Horizontal 3-sum over 8 columns (4 packed u64), warp-shuffle neighbors plus
// scalar halo vH at the warp's interior boundary.
__device__ __forceinline__ void hsum8(const u64 v0, const u64 v1, const u64 v2, const u64 v3,
                                      float vH, int lane, int half,
                                      u64& H0, u64& H1, u64& H2, u64& H3) {
    float f0, f1, f2, f3, f4, f5, f6, f7;
    f2_unpack(v0, f0, f1);
    f2_unpack(v1, f2, f3);
    f2_unpack(v2, f4, f5);
    f2_unpack(v3, f6, f7);
    float up = __shfl_up_sync(0xffffffffu, f7, 1);
    float dn = __shfl_down_sync(0xffffffffu, f0, 1);
    float nl = (lane == 0)  ? (half ? vH : 0.f) : up;
    float nr = (lane == 31) ? (half ? 0.f : vH) : dn;
    u64 L0 = f2_pack(nl, f0);
    u64 L1 = f2_pack(f1, f2);
    u64 L2 = f2_pack(f3, f4);
    u64 L3 = f2_pack(f5, f6);
    u64 R3 = f2_pack(f7, nr);
    H0 = add2(add2(L0, v0), L1);
    H1 = add2(add2(L1, v1), L2);
    H2 = add2(add2(L2, v2), L3);
    H3 = add2(add2(L3, v3), R3);
}

__global__ void __launch_bounds__(128, 4)
loss_fused(const float* __restrict__ X, const float* __restrict__ Y,
           float* __restrict__ out) {
    const int w    = threadIdx.x >> 5;
    const int lane = threadIdx.x & 31;
    const int task  = blockIdx.x * WPB + w;
    const int half  = task & 1;
    const int strip = (task >> 1) & (STRIPS - 1);
    const int plane = task >> 6;
    const int R0 = strip * RPW;
    const int c0 = half * 256 + (lane << 3);

    const float* px = X + (size_t)plane * (IMW * IMH) + c0;
    const float* py = Y + (size_t)plane * (IMW * IMH) + c0;

    const bool hval = (lane == 0) ? (half == 1)
                    : ((lane == 31) ? (half == 0) : false);
    const int hoff = (lane == 0) ? -1 : 8;

    const u64 k9   = f2_set(9.0f);
    const u64 kC1  = f2_set(0.0162f);      // 162 * C1
    const u64 kC2  = f2_set(0.1458f);      // 162 * C2
    const u64 kEPS = f2_set(2.6244e-4f);   // 4 * 6561 * eps

    // 4-slot rolling window of s,d rows (8 cols = 4 u64 each); halo per slot
    // packed as (hs, hd).
    u64 ws[4][4], wdv[4][4];
    u64 whsd[4];

    // L2 prefetch hint for window row j (zero registers).
    auto PF = [&](int j) {
        int gr = R0 - 1 + j;
        gr = (gr < IMH) ? gr : (IMH - 1);   // clamp; only a hint
        const float* ax = px + (size_t)gr * IMW;
        const float* ay = py + (size_t)gr * IMW;
        asm volatile("prefetch.global.L2 [%0];" :: "l"(ax));
        asm volatile("prefetch.global.L2 [%0];" :: "l"(ay));
    };

    // Load row gr = R0-1+j and convert into window slot j&3.
    auto LOADCVT = [&](int j) {
        const int slot = j & 3;
        const int gr = R0 - 1 + j;
        const bool v = ((unsigned)gr < (unsigned)IMH);
        float4 xa = make_float4(0.f, 0.f, 0.f, 0.f), xb = xa, ya = xa, yb = xa;
        float hx = 0.f, hy = 0.f;
        if (v) {
            const float4* p4 = reinterpret_cast<const float4*>(px + (size_t)gr * IMW);
            const float4* q4 = reinterpret_cast<const float4*>(py + (size_t)gr * IMW);
            xa = p4[0]; xb = p4[1];
            ya = q4[0]; yb = q4[1];
            if (hval) {
                hx = px[(size_t)gr * IMW + hoff];
                hy = py[(size_t)gr * IMW + hoff];
            }
        }
        u64 xp0 = f2_pack(xa.x, xa.y), xp1 = f2_pack(xa.z, xa.w);
        u64 xp2 = f2_pack(xb.x, xb.y), xp3 = f2_pack(xb.z, xb.w);
        u64 yp0 = f2_pack(ya.x, ya.y), yp1 = f2_pack(ya.z, ya.w);
        u64 yp2 = f2_pack(yb.x, yb.y), yp3 = f2_pack(yb.z, yb.w);
        ws[slot][0] = add2(xp0, yp0);   wdv[slot][0] = sub2(xp0, yp0);
        ws[slot][1] = add2(xp1, yp1);   wdv[slot][1] = sub2(xp1, yp1);
        ws[slot][2] = add2(xp2, yp2);   wdv[slot][2] = sub2(xp2, yp2);
        ws[slot][3] = add2(xp3, yp3);   wdv[slot][3] = sub2(xp3, yp3);
        whsd[slot] = f2_pack(hx + hy, hx - hy);
    };

    PF(4); PF(5);
    LOADCVT(0); LOADCVT(1); LOADCVT(2); LOADCVT(3);

    u64 mAcc0 = f2_set(0.f), mAcc1 = f2_set(0.f);
    float sA0 = 0.f, sA1 = 0.f;

#pragma unroll
    for (int r = 0; r < RPW; r += 2) {
        const int jA = r & 3, jB = (r + 1) & 3, jC = (r + 2) & 3, jD = (r + 3) & 3;

        // ---- halo vertical sums for both output rows, fully packed ----
        u64 hA = whsd[jA], hB = whsd[jB], hC = whsd[jC], hD = whsd[jD];
        u64 hp  = add2(hB, hC);
        u64 vh1A = add2(hp, hA),  vh1B = add2(hp, hD);
        u64 hq  = fma2(hB, hB, mul2(hC, hC));
        u64 vh2A = fma2(hA, hA, hq), vh2B = fma2(hD, hD, hq);
        float vHsA, vHdA, vHssA, vHddA, vHsB, vHdB, vHssB, vHddB;
        f2_unpack(vh1A, vHsA, vHdA);  f2_unpack(vh2A, vHssA, vHddA);
        f2_unpack(vh1B, vHsB, vHdB);  f2_unpack(vh2B, vHssB, vHddB);

        // ---- shared middle-pair vertical partials ----
        u64 ps[4], pd[4];
#pragma unroll
        for (int k = 0; k < 4; ++k) {
            ps[k] = add2(ws[jB][k],  ws[jC][k]);
            pd[k] = add2(wdv[jB][k], wdv[jC][k]);
        }

        // Process one output row: jx = its distinct window row (jA or jD);
        // (j0,j1,j2) = its three window rows for the squares.
        auto ROW = [&](int jx, int j0, int j1, int j2,
                       float vHs, float vHd, float vHss, float vHdd) {
            u64 T1[4], T2[4];
            {
                u64 Vq[4], Hq[4];
#pragma unroll
                for (int k = 0; k < 4; ++k) Vq[k] = add2(ps[k], ws[jx][k]);
                hsum8(Vq[0], Vq[1], Vq[2], Vq[3], vHs, lane, half,
                      Hq[0], Hq[1], Hq[2], Hq[3]);
                u64 Es[4];
#pragma unroll
                for (int k = 0; k < 4; ++k) Es[k] = mul2(Hq[k], Hq[k]);
#pragma unroll
                for (int k = 0; k < 4; ++k) Vq[k] = add2(pd[k], wdv[jx][k]);
                hsum8(Vq[0], Vq[1], Vq[2], Vq[3], vHd, lane, half,
                      Hq[0], Hq[1], Hq[2], Hq[3]);
#pragma unroll
                for (int k = 0; k < 4; ++k) {
                    u64 F = mul2(Hq[k], Hq[k]);
                    T1[k] = sub2(Es[k], F);
                    T2[k] = add2(Es[k], F);
                }
            }
            u64 Hss[4], Hdd[4];
            {
                u64 Vq[4];
#pragma unroll
                for (int k = 0; k < 4; ++k) {
                    u64 s0 = ws[j0][k], s1 = ws[j1][k], s2 = ws[j2][k];
                    Vq[k] = fma2(s0, s0, fma2(s1, s1, mul2(s2, s2)));
                }
                hsum8(Vq[0], Vq[1], Vq[2], Vq[3], vHss, lane, half,
                      Hss[0], Hss[1], Hss[2], Hss[3]);
#pragma unroll
                for (int k = 0; k < 4; ++k) {
                    u64 d0 = wdv[j0][k], d1 = wdv[j1][k], d2 = wdv[j2][k];
                    Vq[k] = fma2(d0, d0, fma2(d1, d1, mul2(d2, d2)));
                }
                hsum8(Vq[0], Vq[1], Vq[2], Vq[3], vHdd, lane, half,
                      Hdd[0], Hdd[1], Hdd[2], Hdd[3]);
            }
#pragma unroll
            for (int k = 0; k < 4; ++k) {
                u64 N1 = add2(T1[k], kC1);
                u64 D1 = add2(T2[k], kC1);
                u64 U1 = sub2(Hss[k], Hdd[k]);
                u64 U2 = add2(Hss[k], Hdd[k]);
                u64 N2 = sub2(fma2(U1, k9, kC2), T1[k]);
                u64 D2 = sub2(fma2(U2, k9, kC2), T2[k]);
                u64 num = mul2(N1, N2);
                u64 den = fma2(D1, D2, kEPS);
                float n0, n1, d0, d1;
                f2_unpack(num, n0, n1);
                f2_unpack(den, d0, d1);
                sA0 += __fdividef(n0, d0);
                sA1 += __fdividef(n1, d1);
            }
        };

        // Output row r   : window rows (jA, jB, jC), extra row jA
        ROW(jA, jA, jB, jC, vHsA, vHdA, vHssA, vHddA);
        // Output row r+1 : window rows (jB, jC, jD), extra row jD
        ROW(jD, jB, jC, jD, vHsB, vHdB, vHssB, vHddB);

        // ---- MSE: center rows of outputs r and r+1 are slots jB and jC ----
        mAcc0 = fma2(wdv[jB][0], wdv[jB][0], mAcc0);
        mAcc0 = fma2(wdv[jB][1], wdv[jB][1], mAcc0);
        mAcc1 = fma2(wdv[jB][2], wdv[jB][2], mAcc1);
        mAcc1 = fma2(wdv[jB][3], wdv[jB][3], mAcc1);
        mAcc0 = fma2(wdv[jC][0], wdv[jC][0], mAcc0);
        mAcc0 = fma2(wdv[jC][1], wdv[jC][1], mAcc0);
        mAcc1 = fma2(wdv[jC][2], wdv[jC][2], mAcc1);
        mAcc1 = fma2(wdv[jC][3], wdv[jC][3], mAcc1);

        // ---- load the next two window rows (consumed next iteration) ----
        if (r < RPW - 2) {
            LOADCVT(r + 4);
            LOADCVT(r + 5);
            PF(r + 6); PF(r + 7);
        }
    }

    // ---- reductions ----
    float m0, m1, m2, m3;
    f2_unpack(mAcc0, m0, m1);
    f2_unpack(mAcc1, m2, m3);
    float mAcc = (m0 + m1) + (m2 + m3);
    float sAcc = sA0 + sA1;
#pragma unroll
    for (int o = 16; o; o >>= 1) {
        mAcc += __shfl_xor_sync(0xffffffffu, mAcc, o);
        sAcc += __shfl_xor_sync(0xffffffffu, sAcc, o);
    }
    __shared__ float shm[WPB], shs[WPB];
    if (lane == 0) { shm[w] = mAcc; shs[w] = sAcc; }
    __syncthreads();
    if (threadIdx.x == 0) {
        float M = (shm[0] + shm[1]) + (shm[2] + shm[3]);
        float S = (shs[0] + shs[1]) + (shs[2] + shs[3]);
        atomicAdd(&g_mse_acc, M);
        atomicAdd(&g_ssim_acc, S);
        __threadfence();
        unsigned c = atomicInc(&g_cnt, NBLOCKS - 1);   // wraps to 0 on last
        if (c == NBLOCKS - 1) {
            __threadfence();
            float Mt = atomicExch(&g_mse_acc, 0.f);
            float St = atomicExch(&g_ssim_acc, 0.f);
            double mse  = (double)Mt / NTOTD;
            double ssim = (double)St / NTOTD;
            out[0] = (float)(0.8 * mse + 0.2 * (1.0 - ssim));
        }
    }
}

extern "C" void kernel_launch(void* const* d_in, const int* in_sizes, int n_in,
                              void* d_out, int out_size) {
    const float* X = (const float*)d_in[0];
    const float* Y = (const float*)d_in[1];
    loss_fused<<<NBLOCKS, 128>>>(X, Y, (float*)d_out);
}

// round 11
// speedup vs baseline: 1.0772x; 1.0210x over previous
#include <cuda_runtime.h>

// ---------------------------------------------------------------------------
// EnhancedReconstructionLoss: 0.8*MSE + 0.2*(1 - mean(SSIM_map)), fused.
//
// s/d reformulation (s=x+y, d=x-y) -> 4 window sums (Ws,Wd,Wss,Wdd):
//   N1 = (Ws^2-Wd^2) + 162*C1          N2 = 9(Wss-Wdd) - (Ws^2-Wd^2) + 162*C2
//   D1 = (Ws^2+Wd^2) + 162*C1          D2 = 9(Wss+Wdd) - (Ws^2+Wd^2) + 162*C2
//   ssim = N1*N2 / (D1*D2 + 4*6561*eps)
//
// R11: R10's 2-row body + TRUE load decoupling at zero register cost.
// Window slots hold RAW (x,y) rows (16 regs = same as converted); in-place
// CONVERT happens one body-phase after the LDGs, so no long-scoreboard stall
// ever lands on the critical path. Halo converted lazily too.
// ---------------------------------------------------------------------------

typedef unsigned long long u64;

#define IMW 512
#define IMH 512
#define NPLANES 96
#define RPW 16                    // rows per warp-task
#define STRIPS 32                 // 512 / 16
#define WPB 4                     // warps per block
#define NBLOCKS (NPLANES * STRIPS * 2 / WPB)   // 1536
#define NTOTD 25165824.0          // 32*3*512*512

__device__ float g_mse_acc  = 0.f;
__device__ float g_ssim_acc = 0.f;
__device__ unsigned int g_cnt = 0u;

__device__ __forceinline__ u64 f2_pack(float lo, float hi) {
    u64 r; asm("mov.b64 %0, {%1, %2};" : "=l"(r) : "f"(lo), "f"(hi)); return r;
}
__device__ __forceinline__ void f2_unpack(u64 p, float& lo, float& hi) {
    asm("mov.b64 {%0, %1}, %2;" : "=f"(lo), "=f"(hi) : "l"(p));
}
__device__ __forceinline__ u64 f2_set(float v) { return f2_pack(v, v); }
__device__ __forceinline__ u64 add2(u64 a, u64 b) {
    u64 d; asm("add.rn.f32x2 %0, %1, %2;" : "=l"(d) : "l"(a), "l"(b)); return d;
}
__device__ __forceinline__ u64 sub2(u64 a, u64 b) {
    u64 d; asm("sub.rn.f32x2 %0, %1, %2;" : "=l"(d) : "l"(a), "l"(b)); return d;
}
__device__ __forceinline__ u64 mul2(u64 a, u64 b) {
    u64 d; asm("mul.rn.f32x2 %0, %1, %2;" : "=l"(d) : "l"(a), "l"(b)); return d;
}
__device__ __forceinline__ u64 fma2(u64 a, u64 b, u64 c) {
    u64 d; asm("fma.rn.f32x2 %0, %1, %2, %3;" : "=l"(d) : "l"(a), "l"(b), "l"(c)); return d;
}

// Horizontal 3-sum over 8 columns (4 packed u64), warp-shuffle neighbors plus
// scalar halo vH at the warp's interior boundary.
__device__ __forceinline__ void hsum8(const u64 v0, const u64 v1, const u64 v2, const u64 v3,
                                      float vH, int lane, int half,
                                      u64& H0, u64& H1, u64& H2, u64& H3) {
    float f0, f1, f2, f3, f4, f5, f6, f7;
    f2_unpack(v0, f0, f1);
    f2_unpack(v1, f2, f3);
    f2_unpack(v2, f4, f5);
    f2_unpack(v3, f6, f7);
    float up = __shfl_up_sync(0xffffffffu, f7, 1);
    float dn = __shfl_down_sync(0xffffffffu, f0, 1);
    float nl = (lane == 0)  ? (half ? vH : 0.f) : up;
    float nr = (lane == 31) ? (half ? 0.f : vH) : dn;
    u64 L0 = f2_pack(nl, f0);
    u64 L1 = f2_pack(f1, f2);
    u64 L2 = f2_pack(f3, f4);
    u64 L3 = f2_pack(f5, f6);
    u64 R3 = f2_pack(f7, nr);
    H0 = add2(add2(L0, v0), L1);
    H1 = add2(add2(L1, v1), L2);
    H2 = add2(add2(L2, v2), L3);
    H3 = add2(add2(L3, v3), R3);
}

__global__ void __launch_bounds__(128, 4)
loss_fused(const float* __restrict__ X, const float* __restrict__ Y,
           float* __restrict__ out) {
    const int w    = threadIdx.x >> 5;
    const int lane = threadIdx.x & 31;
    const int task  = blockIdx.x * WPB + w;
    const int half  = task & 1;
    const int strip = (task >> 1) & (STRIPS - 1);
    const int plane = task >> 6;
    const int R0 = strip * RPW;
    const int c0 = half * 256 + (lane << 3);

    const float* px = X + (size_t)plane * (IMW * IMH) + c0;
    const float* py = Y + (size_t)plane * (IMW * IMH) + c0;

    const bool hval = (lane == 0) ? (half == 1)
                    : ((lane == 31) ? (half == 0) : false);
    const int hoff = (lane == 0) ? -1 : 8;

    const u64 k9   = f2_set(9.0f);
    const u64 kC1  = f2_set(0.0162f);      // 162 * C1
    const u64 kC2  = f2_set(0.1458f);      // 162 * C2
    const u64 kEPS = f2_set(2.6244e-4f);   // 4 * 6561 * eps

    // 4-slot rolling window. A slot is either RAW (ws=x rows, wdv=y rows,
    // whsd=(hx,hy)) or CONVERTED in place (ws=s, wdv=d, whsd=(hs,hd)).
    u64 ws[4][4], wdv[4][4];
    u64 whsd[4];

    // L2 prefetch hint for window row j (zero registers).
    auto PF = [&](int j) {
        int gr = R0 - 1 + j;
        gr = (gr < IMH) ? gr : (IMH - 1);
        const float* ax = px + (size_t)gr * IMW;
        const float* ay = py + (size_t)gr * IMW;
        asm volatile("prefetch.global.L2 [%0];" :: "l"(ax));
        asm volatile("prefetch.global.L2 [%0];" :: "l"(ay));
    };

    // Load row gr = R0-1+j RAW into slot j&3 (x into ws, y into wdv).
    // Pure LDG + register packing: no arithmetic depends on the loads here.
    auto LOAD_RAW = [&](int j) {
        const int slot = j & 3;
        const int gr = R0 - 1 + j;
        const bool v = ((unsigned)gr < (unsigned)IMH);
        float4 xa = make_float4(0.f, 0.f, 0.f, 0.f), xb = xa, ya = xa, yb = xa;
        float hx = 0.f, hy = 0.f;
        if (v) {
            const float4* p4 = reinterpret_cast<const float4*>(px + (size_t)gr * IMW);
            const float4* q4 = reinterpret_cast<const float4*>(py + (size_t)gr * IMW);
            xa = p4[0]; xb = p4[1];
            ya = q4[0]; yb = q4[1];
            if (hval) {
                hx = px[(size_t)gr * IMW + hoff];
                hy = py[(size_t)gr * IMW + hoff];
            }
        }
        ws[slot][0]  = f2_pack(xa.x, xa.y);  ws[slot][1]  = f2_pack(xa.z, xa.w);
        ws[slot][2]  = f2_pack(xb.x, xb.y);  ws[slot][3]  = f2_pack(xb.z, xb.w);
        wdv[slot][0] = f2_pack(ya.x, ya.y);  wdv[slot][1] = f2_pack(ya.z, ya.w);
        wdv[slot][2] = f2_pack(yb.x, yb.y);  wdv[slot][3] = f2_pack(yb.z, yb.w);
        whsd[slot]   = f2_pack(hx, hy);
    };

    // In-place convert slot j&3 from raw (x,y) to (s,d). Runs one body-phase
    // after LOAD_RAW, so the LDGs are long complete.
    auto CONVERT = [&](int j) {
        const int slot = j & 3;
#pragma unroll
        for (int k = 0; k < 4; ++k) {
            u64 xv = ws[slot][k], yv = wdv[slot][k];
            ws[slot][k]  = add2(xv, yv);
            wdv[slot][k] = sub2(xv, yv);
        }
        float hx, hy;
        f2_unpack(whsd[slot], hx, hy);
        whsd[slot] = f2_pack(hx + hy, hx - hy);
    };

    // Prologue: rows 0,1 loaded+converted; rows 2,3 left RAW; hints for 4,5.
    LOAD_RAW(0); LOAD_RAW(1);
    CONVERT(0);  CONVERT(1);
    LOAD_RAW(2); LOAD_RAW(3);
    PF(4); PF(5);

    u64 mAcc0 = f2_set(0.f), mAcc1 = f2_set(0.f);
    float sA0 = 0.f, sA1 = 0.f;

#pragma unroll
    for (int r = 0; r < RPW; r += 2) {
        const int jA = r & 3, jB = (r + 1) & 3, jC = (r + 2) & 3, jD = (r + 3) & 3;

        // (1) convert row r+2 (raw since last iteration; loads long done)
        CONVERT(r + 2);

        // (2) A-row halo sums + shared pair partials + MSE (rows r, r+1)
        u64 hA = whsd[jA], hB = whsd[jB], hC = whsd[jC];
        u64 hp  = add2(hB, hC);
        u64 hq  = fma2(hB, hB, mul2(hC, hC));
        u64 vh1A = add2(hp, hA);
        u64 vh2A = fma2(hA, hA, hq);
        float vHsA, vHdA, vHssA, vHddA;
        f2_unpack(vh1A, vHsA, vHdA);
        f2_unpack(vh2A, vHssA, vHddA);

        u64 ps[4], pd[4];
#pragma unroll
        for (int k = 0; k < 4; ++k) {
            ps[k] = add2(ws[jB][k],  ws[jC][k]);
            pd[k] = add2(wdv[jB][k], wdv[jC][k]);
        }

        mAcc0 = fma2(wdv[jB][0], wdv[jB][0], mAcc0);
        mAcc0 = fma2(wdv[jB][1], wdv[jB][1], mAcc0);
        mAcc1 = fma2(wdv[jB][2], wdv[jB][2], mAcc1);
        mAcc1 = fma2(wdv[jB][3], wdv[jB][3], mAcc1);
        mAcc0 = fma2(wdv[jC][0], wdv[jC][0], mAcc0);
        mAcc0 = fma2(wdv[jC][1], wdv[jC][1], mAcc0);
        mAcc1 = fma2(wdv[jC][2], wdv[jC][2], mAcc1);
        mAcc1 = fma2(wdv[jC][3], wdv[jC][3], mAcc1);

        // one output row; jx = distinct window slot; (j0,j1,j2) for squares
        auto ROW = [&](int jx, int j0, int j1, int j2,
                       float vHs, float vHd, float vHss, float vHdd) {
            u64 T1[4], T2[4];
            {
                u64 Vq[4], Hq[4];
#pragma unroll
                for (int k = 0; k < 4; ++k) Vq[k] = add2(ps[k], ws[jx][k]);
                hsum8(Vq[0], Vq[1], Vq[2], Vq[3], vHs, lane, half,
                      Hq[0], Hq[1], Hq[2], Hq[3]);
                u64 Es[4];
#pragma unroll
                for (int k = 0; k < 4; ++k) Es[k] = mul2(Hq[k], Hq[k]);
#pragma unroll
                for (int k = 0; k < 4; ++k) Vq[k] = add2(pd[k], wdv[jx][k]);
                hsum8(Vq[0], Vq[1], Vq[2], Vq[3], vHd, lane, half,
                      Hq[0], Hq[1], Hq[2], Hq[3]);
#pragma unroll
                for (int k = 0; k < 4; ++k) {
                    u64 F = mul2(Hq[k], Hq[k]);
                    T1[k] = sub2(Es[k], F);
                    T2[k] = add2(Es[k], F);
                }
            }
            u64 Hss[4], Hdd[4];
            {
                u64 Vq[4];
#pragma unroll
                for (int k = 0; k < 4; ++k) {
                    u64 s0 = ws[j0][k], s1 = ws[j1][k], s2 = ws[j2][k];
                    Vq[k] = fma2(s0, s0, fma2(s1, s1, mul2(s2, s2)));
                }
                hsum8(Vq[0], Vq[1], Vq[2], Vq[3], vHss, lane, half,
                      Hss[0], Hss[1], Hss[2], Hss[3]);
#pragma unroll
                for (int k = 0; k < 4; ++k) {
                    u64 d0 = wdv[j0][k], d1 = wdv[j1][k], d2 = wdv[j2][k];
                    Vq[k] = fma2(d0, d0, fma2(d1, d1, mul2(d2, d2)));
                }
                hsum8(Vq[0], Vq[1], Vq[2], Vq[3], vHdd, lane, half,
                      Hdd[0], Hdd[1], Hdd[2], Hdd[3]);
            }
#pragma unroll
            for (int k = 0; k < 4; ++k) {
                u64 N1 = add2(T1[k], kC1);
                u64 D1 = add2(T2[k], kC1);
                u64 U1 = sub2(Hss[k], Hdd[k]);
                u64 U2 = add2(Hss[k], Hdd[k]);
                u64 N2 = sub2(fma2(U1, k9, kC2), T1[k]);
                u64 D2 = sub2(fma2(U2, k9, kC2), T2[k]);
                u64 num = mul2(N1, N2);
                u64 den = fma2(D1, D2, kEPS);
                float n0, n1, d0, d1;
                f2_unpack(num, n0, n1);
                f2_unpack(den, d0, d1);
                sA0 += __fdividef(n0, d0);
                sA1 += __fdividef(n1, d1);
            }
        };

        // (3) output row r : rows r-1,r,r+1 -> slots jA,jB,jC
        ROW(jA, jA, jB, jC, vHsA, vHdA, vHssA, vHddA);

        // (4) slot jA retired -> load row r+4 raw (consumed next iter step 1)
        if (r < RPW - 2) LOAD_RAW(r + 4);

        // (5) convert row r+3 (raw since last iteration's end)
        CONVERT(r + 3);

        // (5b) B-row halo sums (needs converted hD)
        u64 hD = whsd[jD];
        u64 vh1B = add2(hp, hD);
        u64 vh2B = fma2(hD, hD, hq);
        float vHsB, vHdB, vHssB, vHddB;
        f2_unpack(vh1B, vHsB, vHdB);
        f2_unpack(vh2B, vHssB, vHddB);

        // (6) output row r+1 : rows r,r+1,r+2 -> slots jB,jC,jD
        ROW(jD, jB, jC, jD, vHsB, vHdB, vHssB, vHddB);

        // (7) slot jB retired -> load row r+5 raw; hint two rows beyond
        if (r < RPW - 2) {
            LOAD_RAW(r + 5);
            PF(r + 6); PF(r + 7);
        }
    }

    // ---- reductions ----
    float m0, m1, m2, m3;
    f2_unpack(mAcc0, m0, m1);
    f2_unpack(mAcc1, m2, m3);
    float mAcc = (m0 + m1) + (m2 + m3);
    float sAcc = sA0 + sA1;
#pragma unroll
    for (int o = 16; o; o >>= 1) {
        mAcc += __shfl_xor_sync(0xffffffffu, mAcc, o);
        sAcc += __shfl_xor_sync(0xffffffffu, sAcc, o);
    }
    __shared__ float shm[WPB], shs[WPB];
    if (lane == 0) { shm[w] = mAcc; shs[w] = sAcc; }
    __syncthreads();
    if (threadIdx.x == 0) {
        float M = (shm[0] + shm[1]) + (shm[2] + shm[3]);
        float S = (shs[0] + shs[1]) + (shs[2] + shs[3]);
        atomicAdd(&g_mse_acc, M);
        atomicAdd(&g_ssim_acc, S);
        __threadfence();
        unsigned c = atomicInc(&g_cnt, NBLOCKS - 1);   // wraps to 0 on last
        if (c == NBLOCKS - 1) {
            __threadfence();
            float Mt = atomicExch(&g_mse_acc, 0.f);
            float St = atomicExch(&g_ssim_acc, 0.f);
            double mse  = (double)Mt / NTOTD;
            double ssim = (double)St / NTOTD;
            out[0] = (float)(0.8 * mse + 0.2 * (1.0 - ssim));
        }
    }
}

extern "C" void kernel_launch(void* const* d_in, const int* in_sizes, int n_in,
                              void* d_out, int out_size) {
    const float* X = (const float*)d_in[0];
    const float* Y = (const float*)d_in[1];
    loss_fused<<<NBLOCKS, 128>>>(X, Y, (float*)d_out);
}

// round 12
// speedup vs baseline: 1.1237x; 1.0432x over previous
#include <cuda_runtime.h>

// ---------------------------------------------------------------------------
// EnhancedReconstructionLoss: 0.8*MSE + 0.2*(1 - mean(SSIM_map)), fused.
//
// s/d reformulation (s=x+y, d=x-y) -> 4 window sums (Ws,Wd,Wss,Wdd):
//   N1 = (Ws^2-Wd^2) + 162*C1          N2 = 9(Wss-Wdd) - (Ws^2-Wd^2) + 162*C2
//   D1 = (Ws^2+Wd^2) + 162*C1          D2 = 9(Wss+Wdd) - (Ws^2+Wd^2) + 162*C2
//   ssim = N1*N2 / (D1*D2 + 4*6561*eps)
//
// R12 = R11 (raw-slot decoupled loads, in-place converts) + middle-pair
// SQUARE sharing: qs=sB^2+sC^2, qd=dB^2+dC^2 computed once per iteration,
// reused by both output rows' Vss/Vdd AND by the MSE (center rows are B,C),
// eliminating ~20 packed ops/iteration.
// ---------------------------------------------------------------------------

typedef unsigned long long u64;

#define IMW 512
#define IMH 512
#define NPLANES 96
#define RPW 16                    // rows per warp-task
#define STRIPS 32                 // 512 / 16
#define WPB 4                     // warps per block
#define NBLOCKS (NPLANES * STRIPS * 2 / WPB)   // 1536
#define NTOTD 25165824.0          // 32*3*512*512

__device__ float g_mse_acc  = 0.f;
__device__ float g_ssim_acc = 0.f;
__device__ unsigned int g_cnt = 0u;

__device__ __forceinline__ u64 f2_pack(float lo, float hi) {
    u64 r; asm("mov.b64 %0, {%1, %2};" : "=l"(r) : "f"(lo), "f"(hi)); return r;
}
__device__ __forceinline__ void f2_unpack(u64 p, float& lo, float& hi) {
    asm("mov.b64 {%0, %1}, %2;" : "=f"(lo), "=f"(hi) : "l"(p));
}
__device__ __forceinline__ u64 f2_set(float v) { return f2_pack(v, v); }
__device__ __forceinline__ u64 add2(u64 a, u64 b) {
    u64 d; asm("add.rn.f32x2 %0, %1, %2;" : "=l"(d) : "l"(a), "l"(b)); return d;
}
__device__ __forceinline__ u64 sub2(u64 a, u64 b) {
    u64 d; asm("sub.rn.f32x2 %0, %1, %2;" : "=l"(d) : "l"(a), "l"(b)); return d;
}
__device__ __forceinline__ u64 mul2(u64 a, u64 b) {
    u64 d; asm("mul.rn.f32x2 %0, %1, %2;" : "=l"(d) : "l"(a), "l"(b)); return d;
}
__device__ __forceinline__ u64 fma2(u64 a, u64 b, u64 c) {
    u64 d; asm("fma.rn.f32x2 %0, %1, %2, %3;" : "=l"(d) : "l"(a), "l"(b), "l"(c)); return d;
}

// Horizontal 3-sum over 8 columns (4 packed u64), warp-shuffle neighbors plus
// scalar halo vH at the warp's interior boundary.
__device__ __forceinline__ void hsum8(const u64 v0, const u64 v1, const u64 v2, const u64 v3,
                                      float vH, int lane, int half,
                                      u64& H0, u64& H1, u64& H2, u64& H3) {
    float f0, f1, f2, f3, f4, f5, f6, f7;
    f2_unpack(v0, f0, f1);
    f2_unpack(v1, f2, f3);
    f2_unpack(v2, f4, f5);
    f2_unpack(v3, f6, f7);
    float up = __shfl_up_sync(0xffffffffu, f7, 1);
    float dn = __shfl_down_sync(0xffffffffu, f0, 1);
    float nl = (lane == 0)  ? (half ? vH : 0.f) : up;
    float nr = (lane == 31) ? (half ? 0.f : vH) : dn;
    u64 L0 = f2_pack(nl, f0);
    u64 L1 = f2_pack(f1, f2);
    u64 L2 = f2_pack(f3, f4);
    u64 L3 = f2_pack(f5, f6);
    u64 R3 = f2_pack(f7, nr);
    H0 = add2(add2(L0, v0), L1);
    H1 = add2(add2(L1, v1), L2);
    H2 = add2(add2(L2, v2), L3);
    H3 = add2(add2(L3, v3), R3);
}

__global__ void __launch_bounds__(128, 4)
loss_fused(const float* __restrict__ X, const float* __restrict__ Y,
           float* __restrict__ out) {
    const int w    = threadIdx.x >> 5;
    const int lane = threadIdx.x & 31;
    const int task  = blockIdx.x * WPB + w;
    const int half  = task & 1;
    const int strip = (task >> 1) & (STRIPS - 1);
    const int plane = task >> 6;
    const int R0 = strip * RPW;
    const int c0 = half * 256 + (lane << 3);

    const float* px = X + (size_t)plane * (IMW * IMH) + c0;
    const float* py = Y + (size_t)plane * (IMW * IMH) + c0;

    const bool hval = (lane == 0) ? (half == 1)
                    : ((lane == 31) ? (half == 0) : false);
    const int hoff = (lane == 0) ? -1 : 8;

    const u64 k9   = f2_set(9.0f);
    const u64 kC1  = f2_set(0.0162f);      // 162 * C1
    const u64 kC2  = f2_set(0.1458f);      // 162 * C2
    const u64 kEPS = f2_set(2.6244e-4f);   // 4 * 6561 * eps

    // 4-slot rolling window: RAW (x,y) until CONVERTed in place to (s,d).
    u64 ws[4][4], wdv[4][4];
    u64 whsd[4];

    auto PF = [&](int j) {
        int gr = R0 - 1 + j;
        gr = (gr < IMH) ? gr : (IMH - 1);
        const float* ax = px + (size_t)gr * IMW;
        const float* ay = py + (size_t)gr * IMW;
        asm volatile("prefetch.global.L2 [%0];" :: "l"(ax));
        asm volatile("prefetch.global.L2 [%0];" :: "l"(ay));
    };

    // Load row gr = R0-1+j RAW into slot j&3 (pure LDG + pack).
    auto LOAD_RAW = [&](int j) {
        const int slot = j & 3;
        const int gr = R0 - 1 + j;
        const bool v = ((unsigned)gr < (unsigned)IMH);
        float4 xa = make_float4(0.f, 0.f, 0.f, 0.f), xb = xa, ya = xa, yb = xa;
        float hx = 0.f, hy = 0.f;
        if (v) {
            const float4* p4 = reinterpret_cast<const float4*>(px + (size_t)gr * IMW);
            const float4* q4 = reinterpret_cast<const float4*>(py + (size_t)gr * IMW);
            xa = p4[0]; xb = p4[1];
            ya = q4[0]; yb = q4[1];
            if (hval) {
                hx = px[(size_t)gr * IMW + hoff];
                hy = py[(size_t)gr * IMW + hoff];
            }
        }
        ws[slot][0]  = f2_pack(xa.x, xa.y);  ws[slot][1]  = f2_pack(xa.z, xa.w);
        ws[slot][2]  = f2_pack(xb.x, xb.y);  ws[slot][3]  = f2_pack(xb.z, xb.w);
        wdv[slot][0] = f2_pack(ya.x, ya.y);  wdv[slot][1] = f2_pack(ya.z, ya.w);
        wdv[slot][2] = f2_pack(yb.x, yb.y);  wdv[slot][3] = f2_pack(yb.z, yb.w);
        whsd[slot]   = f2_pack(hx, hy);
    };

    // In-place convert slot j&3 from raw (x,y) to (s,d).
    auto CONVERT = [&](int j) {
        const int slot = j & 3;
#pragma unroll
        for (int k = 0; k < 4; ++k) {
            u64 xv = ws[slot][k], yv = wdv[slot][k];
            ws[slot][k]  = add2(xv, yv);
            wdv[slot][k] = sub2(xv, yv);
        }
        float hx, hy;
        f2_unpack(whsd[slot], hx, hy);
        whsd[slot] = f2_pack(hx + hy, hx - hy);
    };

    LOAD_RAW(0); LOAD_RAW(1);
    CONVERT(0);  CONVERT(1);
    LOAD_RAW(2); LOAD_RAW(3);
    PF(4); PF(5);

    u64 mAcc0 = f2_set(0.f), mAcc1 = f2_set(0.f);
    float sA0 = 0.f, sA1 = 0.f;

#pragma unroll
    for (int r = 0; r < RPW; r += 2) {
        const int jA = r & 3, jB = (r + 1) & 3, jC = (r + 2) & 3, jD = (r + 3) & 3;

        // (1) convert row r+2 (raw since last iteration; loads long done)
        CONVERT(r + 2);

        // (2) halo partials + A-row halo sums
        u64 hA = whsd[jA], hB = whsd[jB], hC = whsd[jC];
        u64 hp  = add2(hB, hC);
        u64 hq  = fma2(hB, hB, mul2(hC, hC));
        u64 vh1A = add2(hp, hA);
        u64 vh2A = fma2(hA, hA, hq);
        float vHsA, vHdA, vHssA, vHddA;
        f2_unpack(vh1A, vHsA, vHdA);
        f2_unpack(vh2A, vHssA, vHddA);

        // (2b) shared middle-pair partials: linear AND squares
        u64 ps[4], pd[4], qs[4], qd[4];
#pragma unroll
        for (int k = 0; k < 4; ++k) {
            u64 sB = ws[jB][k],  sC = ws[jC][k];
            u64 dB = wdv[jB][k], dC = wdv[jC][k];
            ps[k] = add2(sB, sC);
            pd[k] = add2(dB, dC);
            qs[k] = fma2(sB, sB, mul2(sC, sC));
            qd[k] = fma2(dB, dB, mul2(dC, dC));
        }

        // (2c) MSE of center rows B,C comes free from qd
        mAcc0 = add2(mAcc0, qd[0]);
        mAcc0 = add2(mAcc0, qd[1]);
        mAcc1 = add2(mAcc1, qd[2]);
        mAcc1 = add2(mAcc1, qd[3]);

        // one output row; jx = its distinct window slot
        auto ROW = [&](int jx, float vHs, float vHd, float vHss, float vHdd) {
            u64 T1[4], T2[4];
            {
                u64 Vq[4], Hq[4];
#pragma unroll
                for (int k = 0; k < 4; ++k) Vq[k] = add2(ps[k], ws[jx][k]);
                hsum8(Vq[0], Vq[1], Vq[2], Vq[3], vHs, lane, half,
                      Hq[0], Hq[1], Hq[2], Hq[3]);
                u64 Es[4];
#pragma unroll
                for (int k = 0; k < 4; ++k) Es[k] = mul2(Hq[k], Hq[k]);
#pragma unroll
                for (int k = 0; k < 4; ++k) Vq[k] = add2(pd[k], wdv[jx][k]);
                hsum8(Vq[0], Vq[1], Vq[2], Vq[3], vHd, lane, half,
                      Hq[0], Hq[1], Hq[2], Hq[3]);
#pragma unroll
                for (int k = 0; k < 4; ++k) {
                    u64 F = mul2(Hq[k], Hq[k]);
                    T1[k] = sub2(Es[k], F);
                    T2[k] = add2(Es[k], F);
                }
            }
            u64 Hss[4], Hdd[4];
            {
                u64 Vq[4];
#pragma unroll
                for (int k = 0; k < 4; ++k)
                    Vq[k] = fma2(ws[jx][k], ws[jx][k], qs[k]);
                hsum8(Vq[0], Vq[1], Vq[2], Vq[3], vHss, lane, half,
                      Hss[0], Hss[1], Hss[2], Hss[3]);
#pragma unroll
                for (int k = 0; k < 4; ++k)
                    Vq[k] = fma2(wdv[jx][k], wdv[jx][k], qd[k]);
                hsum8(Vq[0], Vq[1], Vq[2], Vq[3], vHdd, lane, half,
                      Hdd[0], Hdd[1], Hdd[2], Hdd[3]);
            }
#pragma unroll
            for (int k = 0; k < 4; ++k) {
                u64 N1 = add2(T1[k], kC1);
                u64 D1 = add2(T2[k], kC1);
                u64 U1 = sub2(Hss[k], Hdd[k]);
                u64 U2 = add2(Hss[k], Hdd[k]);
                u64 N2 = sub2(fma2(U1, k9, kC2), T1[k]);
                u64 D2 = sub2(fma2(U2, k9, kC2), T2[k]);
                u64 num = mul2(N1, N2);
                u64 den = fma2(D1, D2, kEPS);
                float n0, n1, d0, d1;
                f2_unpack(num, n0, n1);
                f2_unpack(den, d0, d1);
                sA0 += __fdividef(n0, d0);
                sA1 += __fdividef(n1, d1);
            }
        };

        // (3) output row r : needs slots jA,jB,jC (all converted)
        ROW(jA, vHsA, vHdA, vHssA, vHddA);

        // (4) slot jA retired -> load row r+4 raw
        if (r < RPW - 2) LOAD_RAW(r + 4);

        // (5) convert row r+3; B-row halo sums
        CONVERT(r + 3);
        u64 hD = whsd[jD];
        u64 vh1B = add2(hp, hD);
        u64 vh2B = fma2(hD, hD, hq);
        float vHsB, vHdB, vHssB, vHddB;
        f2_unpack(vh1B, vHsB, vHdB);
        f2_unpack(vh2B, vHssB, vHddB);

        // (6) output row r+1 : needs slots jB,jC,jD
        ROW(jD, vHsB, vHdB, vHssB, vHddB);

        // (7) slot jB retired -> load row r+5 raw; hints beyond
        if (r < RPW - 2) {
            LOAD_RAW(r + 5);
            PF(r + 6); PF(r + 7);
        }
    }

    // ---- reductions ----
    float m0, m1, m2, m3;
    f2_unpack(mAcc0, m0, m1);
    f2_unpack(mAcc1, m2, m3);
    float mAcc = (m0 + m1) + (m2 + m3);
    float sAcc = sA0 + sA1;
#pragma unroll
    for (int o = 16; o; o >>= 1) {
        mAcc += __shfl_xor_sync(0xffffffffu, mAcc, o);
        sAcc += __shfl_xor_sync(0xffffffffu, sAcc, o);
    }
    __shared__ float shm[WPB], shs[WPB];
    if (lane == 0) { shm[w] = mAcc; shs[w] = sAcc; }
    __syncthreads();
    if (threadIdx.x == 0) {
        float M = (shm[0] + shm[1]) + (shm[2] + shm[3]);
        float S = (shs[0] + shs[1]) + (shs[2] + shs[3]);
        atomicAdd(&g_mse_acc, M);
        atomicAdd(&g_ssim_acc, S);
        __threadfence();
        unsigned c = atomicInc(&g_cnt, NBLOCKS - 1);   // wraps to 0 on last
        if (c == NBLOCKS - 1) {
            __threadfence();
            float Mt = atomicExch(&g_mse_acc, 0.f);
            float St = atomicExch(&g_ssim_acc, 0.f);
            double mse  = (double)Mt / NTOTD;
            double ssim = (double)St / NTOTD;
            out[0] = (float)(0.8 * mse + 0.2 * (1.0 - ssim));
        }
    }
}

extern "C" void kernel_launch(void* const* d_in, const int* in_sizes, int n_in,
                              void* d_out, int out_size) {
    const float* X = (const float*)d_in[0];
    const float* Y = (const float*)d_in[1];
    loss_fused<<<NBLOCKS, 128>>>(X, Y, (float*)d_out);
}